// round 16
// baseline (speedup 1.0000x reference)
#include <cuda_runtime.h>
#include <cstdint>

#define B_   32
#define T_   64
#define FEAT 11664
#define RU   16

#define OFF_FC   0
#define OFF_CONV (B_*T_*2)
#define OFF_FLAT (OFF_CONV + B_*T_*FEAT)
#define OFF_RNN  (OFF_FLAT + B_*T_*FEAT)

typedef unsigned long long ull;

__device__ float  g_pre[B_*T_*RU];
__device__ float2 g_wpack[576];   // [kidx 0..35][nk 0..15] channel pairs

// packed fp32x2 FMA (Blackwell-only PTX)
__device__ __forceinline__ void ffma2(ull &d, ull a, ull b) {
    asm("fma.rn.f32x2 %0, %1, %2, %0;" : "+l"(d) : "l"(a), "l"(b));
}
__device__ __forceinline__ float2 unpk(ull v) {
    float2 r; asm("mov.b64 {%0,%1}, %2;" : "=f"(r.x), "=f"(r.y) : "l"(v)); return r;
}

// --- prep: zero g_pre + pack conv weights in ONE kernel --------------------
__global__ void prep_all(const float* __restrict__ conv_w)
{
    const int i = blockIdx.x * blockDim.x + threadIdx.x;   // 32 x 1024 = 32768
    g_pre[i] = 0.f;                                        // exactly B*T*RU
    if (blockIdx.x == 0 && threadIdx.x < 576) {
        const int e = threadIdx.x;
        const int nk = e & 15, kidx = e >> 4;
        g_wpack[e] = make_float2(conv_w[nk*72 + kidx], conv_w[nk*72 + 36 + kidx]);
    }
}
__global__ void prep_nop() { }

#define TROW 34       // padded tile row stride in float2
#define NKSTR 193     // per-nk staging stride (bank-conflict-free)

// ---------------------------------------------------------------------------
// Conv kernel: warp-balanced 128-thread blocks, channel-paired FFMA2,
// rolling window. R16: ONE barrier per frame (WAR on s_conv[buf] fenced by
// the NEXT frame's barrier via double buffering), FPB=8 (tile/weight load
// amortized, grid 1024).
// ---------------------------------------------------------------------------
#define FPB 8
__global__ __launch_bounds__(128, 5)
void conv_kernel(const float* __restrict__ x,
                 const float* __restrict__ conv_b,
                 float* __restrict__ out_conv, float* __restrict__ out_flat)
{
    __shared__ __align__(16) float2 tile[2][12*TROW];
    __shared__ float2 ws[576];
    __shared__ float  s_conv[2][16*NKSTR];

    const int tid = threadIdx.x;
    const int nk  = tid & 15;
    const int yl  = tid >> 4;            // 0..7
    const int yg  = blockIdx.x;          // 0..3
    const int bt0 = blockIdx.y * FPB;
    const int nrow   = (yg == 3) ? 6 : 7;
    const bool active = yl < nrow;
    const int rowbase = yg * 7;

    for (int e = tid; e < 576; e += 128) ws[e] = g_wpack[e];
    const float bias = conv_b[nk];

    {
        const float* xb = x + (size_t)bt0 * 2048;
        #pragma unroll
        for (int j = 0; j < 3; ++j) {
            const int e  = tid + 128*j;
            const int rg = e >> 5, col = e & 31;
            const int gr = rowbase + rg;
            if (gr < 32)
                tile[0][rg*TROW + col] = make_float2(xb[gr*32 + col],
                                                     xb[1024 + gr*32 + col]);
        }
    }
    __syncthreads();

    const ull* wsu = reinterpret_cast<const ull*>(ws);

    for (int f = 0; f < FPB; ++f) {
        const int buf = f & 1;
        const int bt  = bt0 + f;

        float2 nx[3];
        if (f + 1 < FPB) {
            const float* xb = x + (size_t)(bt + 1) * 2048;
            #pragma unroll
            for (int j = 0; j < 3; ++j) {
                const int e  = tid + 128*j;
                const int rg = e >> 5, col = e & 31;
                const int gr = rowbase + rg;
                if (gr < 32)
                    nx[j] = make_float2(xb[gr*32 + col], xb[1024 + gr*32 + col]);
            }
        }

        if (active) {
            ull acc[27];
            #pragma unroll
            for (int i = 0; i < 27; ++i) acc[i] = 0ull;

            #pragma unroll
            for (int ky = 0; ky < 6; ++ky) {
                const ull* row = reinterpret_cast<const ull*>(&tile[buf][(yl + ky)*TROW]);
                ull wk[6];
                #pragma unroll
                for (int kx = 0; kx < 6; ++kx) wk[kx] = wsu[(ky*6 + kx)*16 + nk];

                ull s[6];
                #pragma unroll
                for (int j = 0; j < 5; ++j) s[j] = row[j];
                #pragma unroll
                for (int i = 0; i < 27; ++i) {
                    s[(i + 5) % 6] = row[i + 5];
                    #pragma unroll
                    for (int kx = 0; kx < 6; ++kx)
                        ffma2(acc[i], s[(i + kx) % 6], wk[kx]);
                }
            }

            const int sb = nk*NKSTR + yl*27;
            #pragma unroll
            for (int i = 0; i < 27; ++i) {
                const float2 p = unpk(acc[i]);
                s_conv[buf][sb + i] = p.x + p.y + bias;
            }
        }

        // commit next frame's tile BEFORE the barrier (reads of tile[1-buf]
        // for frame f-1 were fenced by bar(f-1))
        if (f + 1 < FPB) {
            #pragma unroll
            for (int j = 0; j < 3; ++j) {
                const int e  = tid + 128*j;
                const int rg = e >> 5, col = e & 31;
                if (rowbase + rg < 32) tile[1 - buf][rg*TROW + col] = nx[j];
            }
        }
        __syncthreads();   // SINGLE barrier per frame

        // writeout from s_conv[buf]; next write to this buffer (frame f+2's
        // staging) happens after bar(f+1) -> WAR safe without a 2nd barrier
        {
            const float* sc = s_conv[buf];
            const int count = nrow * 27;
            float* pc = out_conv + (size_t)bt*FEAT + yg*189 + tid;
            float* pf = out_flat + (size_t)bt*FEAT + yg*189 + tid;
            #pragma unroll
            for (int nk2 = 0; nk2 < 16; ++nk2) {
                const float v0 = sc[nk2*NKSTR + tid];
                pc[nk2*729] = v0;
                pf[nk2*729] = fmaxf(v0, 0.f);
            }
            if (tid + 128 < count) {
                #pragma unroll
                for (int nk2 = 0; nk2 < 16; ++nk2) {
                    const float v1 = sc[nk2*NKSTR + 128 + tid];
                    pc[nk2*729 + 128] = v1;
                    pf[nk2*729 + 128] = fmaxf(v1, 0.f);
                }
            }
        }
    }
}

// ---------------------------------------------------------------------------
// Fused adaptive-scan + input-projection (exact R13: broadcast-read dot,
// quad timesteps per barrier, smem partial tree, 16 REDG/block-t).
// ---------------------------------------------------------------------------
__global__ __launch_bounds__(256)
void adproj_kernel(const float* __restrict__ flat, const float* __restrict__ w_ih)
{
    __shared__ __align__(16) float2 row_s[8][256];
    __shared__ float part_s[2][4][8][17];   // [parity][h][warp][r], pad 17
    const int tid  = threadIdx.x;
    const int w    = tid >> 5;
    const int lane = tid & 31;
    const int b    = blockIdx.y;
    const int f0   = blockIdx.x * 512;
    const int nP   = min(512, FEAT - f0) >> 1;   // 256, last block 200
    const int r    = tid & 15;
    const int g    = tid >> 4;
    const bool full = (nP == 256);
    const bool own  = tid < nP;

    ull wreg[16];
    #pragma unroll
    for (int j = 0; j < 16; ++j) {
        const int p = g*16 + j;
        wreg[j] = (p < nP)
            ? *reinterpret_cast<const ull*>(&w_ih[(size_t)r*FEAT + f0 + 2*p])
            : 0ull;
    }

    float ad0 = 0.f, ad1 = 0.f;
    const float* fbase = flat + (size_t)(b*T_)*FEAT + f0 + 2*tid;
    float* preb = g_pre + b*T_*RU;

    float2 v[4], n[4];
    #pragma unroll
    for (int j = 0; j < 4; ++j) { v[j] = make_float2(0.f,0.f); n[j] = v[j]; }
    if (own) {
        #pragma unroll
        for (int j = 0; j < 4; ++j)
            v[j] = *reinterpret_cast<const float2*>(fbase + (size_t)j*FEAT);
        #pragma unroll
        for (int j = 0; j < 4; ++j)
            n[j] = *reinterpret_cast<const float2*>(fbase + (size_t)(4 + j)*FEAT);
    }

    for (int k = 0; k < T_/4; ++k) {
        const int p = (k & 1) * 4;

        float2 m[4];
        #pragma unroll
        for (int j = 0; j < 4; ++j) m[j] = make_float2(0.f,0.f);
        if (own && k + 2 < T_/4) {
            #pragma unroll
            for (int j = 0; j < 4; ++j)
                m[j] = *reinterpret_cast<const float2*>(
                           fbase + (size_t)(4*k + 8 + j)*FEAT);
        }

        if (own) {
            #pragma unroll
            for (int j = 0; j < 4; ++j) {
                const float o0 = fmaxf(v[j].x - ad0, 0.f); ad0 = (ad0 + 0.1f*o0)*0.9f;
                const float o1 = fmaxf(v[j].y - ad1, 0.f); ad1 = (ad1 + 0.1f*o1)*0.9f;
                row_s[p + j][tid] = make_float2(o0, o1);
            }
        }
        __syncthreads();   // fences row_s quad k AND part_s quad k-1

        if (k > 0 && tid < 64) {
            const int hh = tid >> 4, rr = tid & 15;
            const float (*ps)[17] = part_s[(k - 1) & 1][hh];
            float s = 0.f;
            #pragma unroll
            for (int ww = 0; ww < 8; ++ww) s += ps[ww][rr];
            atomicAdd(preb + (4*(k - 1) + hh)*RU + rr, s);
        }

        #pragma unroll
        for (int h = 0; h < 4; ++h) {
            const ull* rpg = reinterpret_cast<const ull*>(row_s[p + h]) + g*16;
            ull acc0 = 0ull, acc1 = 0ull;
            if (full) {
                #pragma unroll
                for (int j = 0; j < 16; j += 4) {
                    const ulonglong2 ra = *reinterpret_cast<const ulonglong2*>(rpg + j);
                    const ulonglong2 rb = *reinterpret_cast<const ulonglong2*>(rpg + j + 2);
                    ffma2(acc0, ra.x, wreg[j]);
                    ffma2(acc1, ra.y, wreg[j + 1]);
                    ffma2(acc0, rb.x, wreg[j + 2]);
                    ffma2(acc1, rb.y, wreg[j + 3]);
                }
            } else {
                #pragma unroll
                for (int j = 0; j < 16; j += 2) {
                    if (g*16 + j < nP) {
                        const ulonglong2 rr2 = *reinterpret_cast<const ulonglong2*>(rpg + j);
                        ffma2(acc0, rr2.x, wreg[j]);
                        ffma2(acc1, rr2.y, wreg[j + 1]);
                    }
                }
            }
            const float2 pa = unpk(acc0);
            const float2 pb = unpk(acc1);
            float a = (pa.x + pb.x) + (pa.y + pb.y);
            a += __shfl_down_sync(0xffffffffu, a, 16);
            if (lane < 16) part_s[k & 1][h][w][lane] = a;
        }
        #pragma unroll
        for (int j = 0; j < 4; ++j) { v[j] = n[j]; n[j] = m[j]; }
    }

    __syncthreads();
    if (tid < 64) {
        const int hh = tid >> 4, rr = tid & 15;
        const float (*ps)[17] = part_s[(T_/4 - 1) & 1][hh];
        float s = 0.f;
        #pragma unroll
        for (int ww = 0; ww < 8; ++ww) s += ps[ww][rr];
        atomicAdd(preb + (T_ - 4 + hh)*RU + rr, s);
    }
}

// ---------------------------------------------------------------------------
// SimpleRNN(16) with adaptation; g_pre strip prefetched. FC separate.
// ---------------------------------------------------------------------------
__global__ __launch_bounds__(32)
void rnn_kernel(const float* __restrict__ w_hh,
                const float* __restrict__ b_ih,
                const float* __restrict__ b_hh,
                float* __restrict__ out_rnn)
{
    const int b    = blockIdx.x;
    const int lane = threadIdx.x;
    const int r    = lane & 15;
    const bool act = lane < 16;

    float whh[16];
    #pragma unroll
    for (int j = 0; j < 16; ++j) whh[j] = w_hh[r*16 + j];
    const float bc = b_ih[r] + b_hh[r];

    float pre_t[T_];
    #pragma unroll
    for (int t = 0; t < T_; ++t)
        pre_t[t] = g_pre[(b*T_ + t)*RU + r];

    float h = 0.f, ad = 0.f;
    #pragma unroll 4
    for (int t = 0; t < T_; ++t) {
        float pre = pre_t[t] + bc;

        float p[16];
        #pragma unroll
        for (int j = 0; j < 16; ++j)
            p[j] = whh[j] * __shfl_sync(0xffffffffu, h, j);
        #pragma unroll
        for (int s2 = 1; s2 < 16; s2 <<= 1)
            #pragma unroll
            for (int j = 0; j < 16; j += 2*s2)
                p[j] += p[j + s2];
        pre += p[0];

        const float a = fmaxf(pre - ad, 0.f);
        ad = (ad + 0.4f*a) * 0.9f;
        h  = act ? a : 0.f;
        if (act) out_rnn[(b*T_ + t)*RU + r] = h;
    }
}

__global__ __launch_bounds__(256)
void fc_kernel(const float* __restrict__ fc_w, const float* __restrict__ fc_b,
               const float* __restrict__ rnn, float* __restrict__ out_fc)
{
    const int i = blockIdx.x * blockDim.x + threadIdx.x;
    if (i < B_*T_*2) {
        const int bt = i >> 1, o = i & 1;
        const float* h = rnn + bt*RU;
        float acc = fc_b[o];
        #pragma unroll
        for (int j = 0; j < 16; ++j)
            acc = fmaf(h[j], fc_w[o*16 + j], acc);
        out_fc[i] = acc;
    }
}

// ---------------------------------------------------------------------------
extern "C" void kernel_launch(void* const* d_in, const int* in_sizes, int n_in,
                              void* d_out, int out_size)
{
    const float* x      = (const float*)d_in[0];
    const float* conv_w = (const float*)d_in[1];
    const float* conv_b = (const float*)d_in[2];
    const float* w_ih   = (const float*)d_in[3];
    const float* w_hh   = (const float*)d_in[4];
    const float* b_ih   = (const float*)d_in[5];
    const float* b_hh   = (const float*)d_in[6];
    const float* fc_w   = (const float*)d_in[7];
    const float* fc_b   = (const float*)d_in[8];
    float* out = (float*)d_out;

    cudaFuncSetAttribute(conv_kernel,
                         cudaFuncAttributePreferredSharedMemoryCarveout, 100);

    prep_all<<<32, 1024>>>(conv_w);           // launch 1 (zero + wpack)
    prep_nop<<<1, 32>>>();                    // launch 2
    conv_kernel<<<dim3(4, (B_*T_)/FPB), 128>>>(x, conv_b,          // launch 3
                                               out + OFF_CONV, out + OFF_FLAT);
    adproj_kernel<<<dim3(23, B_), 256>>>(out + OFF_FLAT, w_ih);    // launch 4 <- ncu capture slot
    rnn_kernel<<<32, 32>>>(w_hh, b_ih, b_hh, out + OFF_RNN);
    fc_kernel<<<16, 256>>>(fc_w, fc_b, out + OFF_RNN, out + OFF_FC);
}

// round 17
// speedup vs baseline: 1.6420x; 1.6420x over previous
#include <cuda_runtime.h>
#include <cstdint>

#define B_   32
#define T_   64
#define FEAT 11664
#define RU   16

#define OFF_FC   0
#define OFF_CONV (B_*T_*2)
#define OFF_FLAT (OFF_CONV + B_*T_*FEAT)
#define OFF_RNN  (OFF_FLAT + B_*T_*FEAT)

typedef unsigned long long ull;

__device__ float  g_pre[B_*T_*RU];
__device__ float2 g_wpack[576];   // [kidx 0..35][nk 0..15] channel pairs

// packed fp32x2 FMA (Blackwell-only PTX)
__device__ __forceinline__ void ffma2(ull &d, ull a, ull b) {
    asm("fma.rn.f32x2 %0, %1, %2, %0;" : "+l"(d) : "l"(a), "l"(b));
}
__device__ __forceinline__ float2 unpk(ull v) {
    float2 r; asm("mov.b64 {%0,%1}, %2;" : "=f"(r.x), "=f"(r.y) : "l"(v)); return r;
}

// --- prep: zero g_pre + pack conv weights in ONE kernel --------------------
__global__ void prep_all(const float* __restrict__ conv_w)
{
    const int i = blockIdx.x * blockDim.x + threadIdx.x;   // 32768 = B*T*RU
    g_pre[i] = 0.f;
    if (blockIdx.x == 0 && threadIdx.x < 576) {
        const int e = threadIdx.x;
        const int nk = e & 15, kidx = e >> 4;
        g_wpack[e] = make_float2(conv_w[nk*72 + kidx], conv_w[nk*72 + 36 + kidx]);
    }
}
__global__ void prep_nop() { }

#define TROW 34       // padded tile row stride in float2
#define NKSTR 193     // per-nk staging stride (bank-conflict-free)

// ---------------------------------------------------------------------------
// Conv kernel: warp-balanced 128-thread blocks, channel-paired FFMA2,
// rolling window. FPB=4 / grid 2048 (R11 wave structure), ONE barrier per
// frame (WAR on s_conv[buf] fenced by the next frame's barrier via parity).
// ---------------------------------------------------------------------------
#define FPB 4
__global__ __launch_bounds__(128, 5)
void conv_kernel(const float* __restrict__ x,
                 const float* __restrict__ conv_b,
                 float* __restrict__ out_conv, float* __restrict__ out_flat)
{
    __shared__ __align__(16) float2 tile[2][12*TROW];
    __shared__ float2 ws[576];
    __shared__ float  s_conv[2][16*NKSTR];

    const int tid = threadIdx.x;
    const int nk  = tid & 15;
    const int yl  = tid >> 4;            // 0..7
    const int yg  = blockIdx.x;          // 0..3
    const int bt0 = blockIdx.y * FPB;
    const int nrow   = (yg == 3) ? 6 : 7;
    const bool active = yl < nrow;
    const int rowbase = yg * 7;

    for (int e = tid; e < 576; e += 128) ws[e] = g_wpack[e];
    const float bias = conv_b[nk];

    {
        const float* xb = x + (size_t)bt0 * 2048;
        #pragma unroll
        for (int j = 0; j < 3; ++j) {
            const int e  = tid + 128*j;
            const int rg = e >> 5, col = e & 31;
            const int gr = rowbase + rg;
            if (gr < 32)
                tile[0][rg*TROW + col] = make_float2(xb[gr*32 + col],
                                                     xb[1024 + gr*32 + col]);
        }
    }
    __syncthreads();

    const ull* wsu = reinterpret_cast<const ull*>(ws);

    for (int f = 0; f < FPB; ++f) {
        const int buf = f & 1;
        const int bt  = bt0 + f;

        float2 nx[3];
        if (f + 1 < FPB) {
            const float* xb = x + (size_t)(bt + 1) * 2048;
            #pragma unroll
            for (int j = 0; j < 3; ++j) {
                const int e  = tid + 128*j;
                const int rg = e >> 5, col = e & 31;
                const int gr = rowbase + rg;
                if (gr < 32)
                    nx[j] = make_float2(xb[gr*32 + col], xb[1024 + gr*32 + col]);
            }
        }

        if (active) {
            ull acc[27];
            #pragma unroll
            for (int i = 0; i < 27; ++i) acc[i] = 0ull;

            #pragma unroll
            for (int ky = 0; ky < 6; ++ky) {
                const ull* row = reinterpret_cast<const ull*>(&tile[buf][(yl + ky)*TROW]);
                ull wk[6];
                #pragma unroll
                for (int kx = 0; kx < 6; ++kx) wk[kx] = wsu[(ky*6 + kx)*16 + nk];

                ull s[6];
                #pragma unroll
                for (int j = 0; j < 5; ++j) s[j] = row[j];
                #pragma unroll
                for (int i = 0; i < 27; ++i) {
                    s[(i + 5) % 6] = row[i + 5];
                    #pragma unroll
                    for (int kx = 0; kx < 6; ++kx)
                        ffma2(acc[i], s[(i + kx) % 6], wk[kx]);
                }
            }

            const int sb = nk*NKSTR + yl*27;
            #pragma unroll
            for (int i = 0; i < 27; ++i) {
                const float2 p = unpk(acc[i]);
                s_conv[buf][sb + i] = p.x + p.y + bias;
            }
        }

        if (f + 1 < FPB) {
            #pragma unroll
            for (int j = 0; j < 3; ++j) {
                const int e  = tid + 128*j;
                const int rg = e >> 5, col = e & 31;
                if (rowbase + rg < 32) tile[1 - buf][rg*TROW + col] = nx[j];
            }
        }
        __syncthreads();   // single barrier per frame

        {
            const float* sc = s_conv[buf];
            const int count = nrow * 27;
            float* pc = out_conv + (size_t)bt*FEAT + yg*189 + tid;
            float* pf = out_flat + (size_t)bt*FEAT + yg*189 + tid;
            #pragma unroll
            for (int nk2 = 0; nk2 < 16; ++nk2) {
                const float v0 = sc[nk2*NKSTR + tid];
                pc[nk2*729] = v0;
                pf[nk2*729] = fmaxf(v0, 0.f);
            }
            if (tid + 128 < count) {
                #pragma unroll
                for (int nk2 = 0; nk2 < 16; ++nk2) {
                    const float v1 = sc[nk2*NKSTR + 128 + tid];
                    pc[nk2*729 + 128] = v1;
                    pf[nk2*729 + 128] = fmaxf(v1, 0.f);
                }
            }
        }
    }
}

// ---------------------------------------------------------------------------
// Fused adaptive-scan + input-projection (exact R13).
// ---------------------------------------------------------------------------
__global__ __launch_bounds__(256)
void adproj_kernel(const float* __restrict__ flat, const float* __restrict__ w_ih)
{
    __shared__ __align__(16) float2 row_s[8][256];
    __shared__ float part_s[2][4][8][17];
    const int tid  = threadIdx.x;
    const int w    = tid >> 5;
    const int lane = tid & 31;
    const int b    = blockIdx.y;
    const int f0   = blockIdx.x * 512;
    const int nP   = min(512, FEAT - f0) >> 1;
    const int r    = tid & 15;
    const int g    = tid >> 4;
    const bool full = (nP == 256);
    const bool own  = tid < nP;

    ull wreg[16];
    #pragma unroll
    for (int j = 0; j < 16; ++j) {
        const int p = g*16 + j;
        wreg[j] = (p < nP)
            ? *reinterpret_cast<const ull*>(&w_ih[(size_t)r*FEAT + f0 + 2*p])
            : 0ull;
    }

    float ad0 = 0.f, ad1 = 0.f;
    const float* fbase = flat + (size_t)(b*T_)*FEAT + f0 + 2*tid;
    float* preb = g_pre + b*T_*RU;

    float2 v[4], n[4];
    #pragma unroll
    for (int j = 0; j < 4; ++j) { v[j] = make_float2(0.f,0.f); n[j] = v[j]; }
    if (own) {
        #pragma unroll
        for (int j = 0; j < 4; ++j)
            v[j] = *reinterpret_cast<const float2*>(fbase + (size_t)j*FEAT);
        #pragma unroll
        for (int j = 0; j < 4; ++j)
            n[j] = *reinterpret_cast<const float2*>(fbase + (size_t)(4 + j)*FEAT);
    }

    for (int k = 0; k < T_/4; ++k) {
        const int p = (k & 1) * 4;

        float2 m[4];
        #pragma unroll
        for (int j = 0; j < 4; ++j) m[j] = make_float2(0.f,0.f);
        if (own && k + 2 < T_/4) {
            #pragma unroll
            for (int j = 0; j < 4; ++j)
                m[j] = *reinterpret_cast<const float2*>(
                           fbase + (size_t)(4*k + 8 + j)*FEAT);
        }

        if (own) {
            #pragma unroll
            for (int j = 0; j < 4; ++j) {
                const float o0 = fmaxf(v[j].x - ad0, 0.f); ad0 = (ad0 + 0.1f*o0)*0.9f;
                const float o1 = fmaxf(v[j].y - ad1, 0.f); ad1 = (ad1 + 0.1f*o1)*0.9f;
                row_s[p + j][tid] = make_float2(o0, o1);
            }
        }
        __syncthreads();

        if (k > 0 && tid < 64) {
            const int hh = tid >> 4, rr = tid & 15;
            const float (*ps)[17] = part_s[(k - 1) & 1][hh];
            float s = 0.f;
            #pragma unroll
            for (int ww = 0; ww < 8; ++ww) s += ps[ww][rr];
            atomicAdd(preb + (4*(k - 1) + hh)*RU + rr, s);
        }

        #pragma unroll
        for (int h = 0; h < 4; ++h) {
            const ull* rpg = reinterpret_cast<const ull*>(row_s[p + h]) + g*16;
            ull acc0 = 0ull, acc1 = 0ull;
            if (full) {
                #pragma unroll
                for (int j = 0; j < 16; j += 4) {
                    const ulonglong2 ra = *reinterpret_cast<const ulonglong2*>(rpg + j);
                    const ulonglong2 rb = *reinterpret_cast<const ulonglong2*>(rpg + j + 2);
                    ffma2(acc0, ra.x, wreg[j]);
                    ffma2(acc1, ra.y, wreg[j + 1]);
                    ffma2(acc0, rb.x, wreg[j + 2]);
                    ffma2(acc1, rb.y, wreg[j + 3]);
                }
            } else {
                #pragma unroll
                for (int j = 0; j < 16; j += 2) {
                    if (g*16 + j < nP) {
                        const ulonglong2 rr2 = *reinterpret_cast<const ulonglong2*>(rpg + j);
                        ffma2(acc0, rr2.x, wreg[j]);
                        ffma2(acc1, rr2.y, wreg[j + 1]);
                    }
                }
            }
            const float2 pa = unpk(acc0);
            const float2 pb = unpk(acc1);
            float a = (pa.x + pb.x) + (pa.y + pb.y);
            a += __shfl_down_sync(0xffffffffu, a, 16);
            if (lane < 16) part_s[k & 1][h][w][lane] = a;
        }
        #pragma unroll
        for (int j = 0; j < 4; ++j) { v[j] = n[j]; n[j] = m[j]; }
    }

    __syncthreads();
    if (tid < 64) {
        const int hh = tid >> 4, rr = tid & 15;
        const float (*ps)[17] = part_s[(T_/4 - 1) & 1][hh];
        float s = 0.f;
        #pragma unroll
        for (int ww = 0; ww < 8; ++ww) s += ps[ww][rr];
        atomicAdd(preb + (T_ - 4 + hh)*RU + rr, s);
    }
}

// ---------------------------------------------------------------------------
// SimpleRNN(16) with adaptation; g_pre strip prefetched. FC separate.
// ---------------------------------------------------------------------------
__global__ __launch_bounds__(32)
void rnn_kernel(const float* __restrict__ w_hh,
                const float* __restrict__ b_ih,
                const float* __restrict__ b_hh,
                float* __restrict__ out_rnn)
{
    const int b    = blockIdx.x;
    const int lane = threadIdx.x;
    const int r    = lane & 15;
    const bool act = lane < 16;

    float whh[16];
    #pragma unroll
    for (int j = 0; j < 16; ++j) whh[j] = w_hh[r*16 + j];
    const float bc = b_ih[r] + b_hh[r];

    float pre_t[T_];
    #pragma unroll
    for (int t = 0; t < T_; ++t)
        pre_t[t] = g_pre[(b*T_ + t)*RU + r];

    float h = 0.f, ad = 0.f;
    #pragma unroll 4
    for (int t = 0; t < T_; ++t) {
        float pre = pre_t[t] + bc;

        float p[16];
        #pragma unroll
        for (int j = 0; j < 16; ++j)
            p[j] = whh[j] * __shfl_sync(0xffffffffu, h, j);
        #pragma unroll
        for (int s2 = 1; s2 < 16; s2 <<= 1)
            #pragma unroll
            for (int j = 0; j < 16; j += 2*s2)
                p[j] += p[j + s2];
        pre += p[0];

        const float a = fmaxf(pre - ad, 0.f);
        ad = (ad + 0.4f*a) * 0.9f;
        h  = act ? a : 0.f;
        if (act) out_rnn[(b*T_ + t)*RU + r] = h;
    }
}

__global__ __launch_bounds__(256)
void fc_kernel(const float* __restrict__ fc_w, const float* __restrict__ fc_b,
               const float* __restrict__ rnn, float* __restrict__ out_fc)
{
    const int i = blockIdx.x * blockDim.x + threadIdx.x;
    if (i < B_*T_*2) {
        const int bt = i >> 1, o = i & 1;
        const float* h = rnn + bt*RU;
        float acc = fc_b[o];
        #pragma unroll
        for (int j = 0; j < 16; ++j)
            acc = fmaf(h[j], fc_w[o*16 + j], acc);
        out_fc[i] = acc;
    }
}

// ---------------------------------------------------------------------------
extern "C" void kernel_launch(void* const* d_in, const int* in_sizes, int n_in,
                              void* d_out, int out_size)
{
    const float* x      = (const float*)d_in[0];
    const float* conv_w = (const float*)d_in[1];
    const float* conv_b = (const float*)d_in[2];
    const float* w_ih   = (const float*)d_in[3];
    const float* w_hh   = (const float*)d_in[4];
    const float* b_ih   = (const float*)d_in[5];
    const float* b_hh   = (const float*)d_in[6];
    const float* fc_w   = (const float*)d_in[7];
    const float* fc_b   = (const float*)d_in[8];
    float* out = (float*)d_out;

    cudaFuncSetAttribute(conv_kernel,
                         cudaFuncAttributePreferredSharedMemoryCarveout, 100);

    prep_all<<<32, 1024>>>(conv_w);           // launch 1
    prep_nop<<<1, 32>>>();                    // launch 2
    conv_kernel<<<dim3(4, (B_*T_)/FPB), 128>>>(x, conv_b,          // launch 3
                                               out + OFF_CONV, out + OFF_FLAT);
    adproj_kernel<<<dim3(23, B_), 256>>>(out + OFF_FLAT, w_ih);    // launch 4 <- ncu capture slot
    rnn_kernel<<<32, 32>>>(w_hh, b_ih, b_hh, out + OFF_RNN);
    fc_kernel<<<16, 256>>>(fc_w, fc_b, out + OFF_RNN, out + OFF_FC);
}